// round 8
// baseline (speedup 1.0000x reference)
#include <cuda_runtime.h>

#define NB 2
#define N1 4096
#define N2 16384
#define CF 64
#define KNN 8

#define BKN  512                  // x-buckets per batch
#define NBK  (NB * BKN)
#define XMIN -4.2f
#define BW   (8.4f / 512.0f)
#define BINV (512.0f / 8.4f)

// Scratch (static __device__ arrays per allocation rules)
__device__ int    g_bcnt[NBK], g_bcur[NBK];
__device__ int    g_tcid[NB * N1];
__device__ int2   g_bk[NBK];                // (offset, count) per bucket
__device__ float4 g_spts[NB * N1];          // bucket-sorted pts, w = orig idx bits
__device__ float  g_gtab[NB * N1 * CF];     // W1_feat@feat + W1_xyz@xyz1 + b1
__device__ int    g_idx[NB * N2 * KNN];     // knn indices (original index space)

__device__ __forceinline__ int xbucket(float x) {
    return min(max(__float2int_rd((x - XMIN) * BINV), 0), BKN - 1);
}

// ---------------------------------------------------------------------------
// bucket build: zero -> histogram -> scan -> scatter
// ---------------------------------------------------------------------------
__global__ void zero_kernel() {
    int i = threadIdx.x + blockIdx.x * 1024;
    if (i < NBK) { g_bcnt[i] = 0; g_bcur[i] = 0; }
}

__global__ void hist_kernel(const float* __restrict__ xyz1) {
    int i = blockIdx.x * 256 + threadIdx.x;
    if (i >= NB * N1) return;
    int b = i >> 12, j = i & (N1 - 1);
    float x = xyz1[(size_t)b * 3 * N1 + j];
    int cid = b * BKN + xbucket(x);
    g_tcid[i] = cid;
    atomicAdd(&g_bcnt[cid], 1);
}

__global__ void __launch_bounds__(512) bscan_kernel() {
    __shared__ int sh[BKN];
    int b = blockIdx.x, t = threadIdx.x;
    int v = g_bcnt[b * BKN + t];
    sh[t] = v;
    __syncthreads();
#pragma unroll
    for (int off = 1; off < BKN; off <<= 1) {
        int u = (t >= off) ? sh[t - off] : 0;
        __syncthreads();
        sh[t] += u;
        __syncthreads();
    }
    g_bk[b * BKN + t] = make_int2(sh[t] - v, v);   // exclusive offset, count
}

__global__ void scatter_kernel(const float* __restrict__ xyz1) {
    int i = blockIdx.x * 256 + threadIdx.x;
    if (i >= NB * N1) return;
    int b = i >> 12, j = i & (N1 - 1);
    const float* p = xyz1 + (size_t)b * 3 * N1;
    float x = p[j], y = p[N1 + j], z = p[2 * N1 + j];
    int cid = g_tcid[i];
    int pos = g_bk[cid].x + atomicAdd(&g_bcur[cid], 1);
    g_spts[b * N1 + pos] = make_float4(x, y, z, __int_as_float(j));
}

// ---------------------------------------------------------------------------
// Kernel 2: per-target transform  g[b][j][o] = sum_c W1[o][c]*in[c] + b1[o]
// ---------------------------------------------------------------------------
__global__ void __launch_bounds__(256) gmat_kernel(const float* __restrict__ feat1,
                                                   const float* __restrict__ xyz1,
                                                   const float* __restrict__ W1,
                                                   const float* __restrict__ b1) {
    __shared__ __align__(16) float sIn[67 * 64];
    __shared__ float sW[64 * 67];
    __shared__ float sB[64];

    int b  = blockIdx.x >> 6;
    int j0 = (blockIdx.x & 63) * 64;
    int t  = threadIdx.x;

    for (int i = t; i < 64 * 67; i += 256) sW[i] = W1[i];
    if (t < 64) sB[t] = b1[t];

    const float* fb = feat1 + (size_t)b * CF * N1;
    for (int i = t; i < 64 * 64; i += 256) {
        int c = i >> 6, j = i & 63;
        sIn[c * 64 + j] = fb[c * N1 + j0 + j];
    }
    const float* xb = xyz1 + (size_t)b * 3 * N1;
    if (t < 3 * 64) {
        int c = t >> 6, j = t & 63;
        sIn[(64 + c) * 64 + j] = xb[c * N1 + j0 + j];
    }
    __syncthreads();

    int o = t & 63, jg = t >> 6;
    float acc[16];
    float bb = sB[o];
#pragma unroll
    for (int ii = 0; ii < 16; ii++) acc[ii] = bb;

    for (int c = 0; c < 67; c++) {
        float w = sW[o * 67 + c];
        const float4* in4 = (const float4*)(sIn + c * 64 + jg * 16);
#pragma unroll
        for (int q4 = 0; q4 < 4; q4++) {
            float4 v = in4[q4];
            acc[q4 * 4 + 0] = fmaf(w, v.x, acc[q4 * 4 + 0]);
            acc[q4 * 4 + 1] = fmaf(w, v.y, acc[q4 * 4 + 1]);
            acc[q4 * 4 + 2] = fmaf(w, v.z, acc[q4 * 4 + 2]);
            acc[q4 * 4 + 3] = fmaf(w, v.w, acc[q4 * 4 + 3]);
        }
    }

    float* gp = g_gtab + ((size_t)b * N1 + j0 + jg * 16) * CF + o;
#pragma unroll
    for (int ii = 0; ii < 16; ii++) gp[ii * CF] = acc[ii];
}

// ---------------------------------------------------------------------------
// Kernel 3: top-8 KNN, one warp per query, bucket two-pointer window.
// Warm start: full-warp bitonic sort of the center bucket's first 32 targets
// seeds the distributed top-8 (kills the insert-event flood). Expansion is
// bucket-at-a-time with exact bucket-edge bounds.
// ---------------------------------------------------------------------------
__device__ __forceinline__ void scan_chunk(const float4* __restrict__ SP,
                                           int base, int c,
                                           float qx, float qy, float qz,
                                           float& dk_own, int& ik_own,
                                           float& dk7, int lane) {
    const unsigned FULL = 0xffffffffu;
    float d = 3.4e38f; int iw = 0;
    if (lane < c) {
        float4 p = SP[base + lane];
        float dx = p.x - qx, dy = p.y - qy, dz = p.z - qz;
        d = fmaf(dz, dz, fmaf(dy, dy, dx * dx));
        iw = __float_as_int(p.w);
    }
    unsigned m = __ballot_sync(FULL, d < dk7);
    while (m) {                            // warp-uniform candidate loop
        int src = __ffs(m) - 1;
        m &= m - 1;
        float dc = __shfl_sync(FULL, d, src);
        if (dc < dk7) {                    // recheck vs tightened threshold
            int jc = __shfl_sync(FULL, iw, src);
            unsigned gt = __ballot_sync(FULL, (lane < 8) && (dk_own > dc));
            int pos = __ffs(gt) - 1;
            float upd = __shfl_up_sync(FULL, dk_own, 1);
            int   upj = __shfl_up_sync(FULL, ik_own, 1);
            if (lane < 8) {
                if (lane == pos)     { dk_own = dc;  ik_own = jc;  }
                else if (lane > pos) { dk_own = upd; ik_own = upj; }
            }
            dk7 = __shfl_sync(FULL, dk_own, 7);
        }
    }
}

__global__ void __launch_bounds__(512) knn_kernel(const float* __restrict__ xyz2) {
    const unsigned FULL = 0xffffffffu;
    int t    = threadIdx.x;
    int lane = t & 31;
    int w    = t >> 5;               // 0..15 : query within block
    int b    = blockIdx.x >> 10;     // 1024 blocks per batch
    int q    = ((blockIdx.x & 1023) << 4) + w;

    const float* xq = xyz2 + (size_t)b * 3 * N2;
    float qx = xq[q], qy = xq[N2 + q], qz = xq[2 * N2 + q];

    const float4* SP  = g_spts + b * N1;
    const int2*   BKT = g_bk   + b * BKN;

    int ib = xbucket(qx);
    int2 cb = BKT[ib];

    // --- warm start: bitonic sort first <=32 targets of the center bucket ---
    float d = 3.4e38f; int id = 0;
    {
        int c = min(cb.y, 32);
        if (lane < c) {
            float4 p = SP[cb.x + lane];
            float dx = p.x - qx, dy = p.y - qy, dz = p.z - qz;
            d = fmaf(dz, dz, fmaf(dy, dy, dx * dx));
            id = __float_as_int(p.w);
        }
#pragma unroll
        for (int k = 2; k <= 32; k <<= 1) {
#pragma unroll
            for (int j = k >> 1; j > 0; j >>= 1) {
                float od = __shfl_xor_sync(FULL, d, j);
                int   oi = __shfl_xor_sync(FULL, id, j);
                bool takeMin = ((lane & j) == 0) == ((lane & k) == 0);
                if ((od < d) == takeMin) { d = od; id = oi; }
            }
        }
    }
    float dk_own = d;                // lane r (r<8) holds list element r, ascending
    int   ik_own = id;               // original target index
    float dk7    = __shfl_sync(FULL, d, 7);

    // leftover of center bucket
    for (int o = 32; o < cb.y; o += 32)
        scan_chunk(SP, cb.x + o, min(cb.y - o, 32), qx, qy, qz,
                   dk_own, ik_own, dk7, lane);

    // --- two-pointer bucket expansion with exact edge bounds ---
    int bl = ib, br = ib;
#pragma unroll 1
    while (bl > 0 || br < BKN - 1) {
        float gl = (bl > 0)       ? qx - (XMIN + bl * BW)       : 3.4e38f;
        float gr = (br < BKN - 1) ? (XMIN + (br + 1) * BW) - qx : 3.4e38f;
        bool left = gl <= gr;
        float gap = fmaxf((left ? gl : gr) - 1e-5f, 0.f);
        if (gap * gap > dk7) break;
        int nb = left ? --bl : ++br;
        int2 bb = BKT[nb];
        for (int o = 0; o < bb.y; o += 32)
            scan_chunk(SP, bb.x + o, min(bb.y - o, 32), qx, qy, qz,
                       dk_own, ik_own, dk7, lane);
    }

    if (lane < 8)
        g_idx[((size_t)b * N2 + q) * KNN + lane] = ik_own;
}

// ---------------------------------------------------------------------------
// Kernel 4: finalize, 4 sub-threads per query (16 channels each).
// h_n = lrelu(g[idx_n] - W1_xyz @ q);  w_j[n] = W2[j].h_n  (b2 cancels);
// softmax over n; dot with flow.
// ---------------------------------------------------------------------------
__device__ __forceinline__ float softmax_dot(const float (&w)[8],
                                             const float* __restrict__ f,
                                             const int (&ik)[8]) {
    float m = w[0];
#pragma unroll
    for (int n = 1; n < 8; n++) m = fmaxf(m, w[n]);
    float s = 0.f, acc = 0.f;
#pragma unroll
    for (int n = 0; n < 8; n++) {
        float e = __expf(w[n] - m);
        s += e;
        acc = fmaf(e, __ldg(f + ik[n]), acc);
    }
    return acc / s;
}

__global__ void __launch_bounds__(256) up_kernel(const float* __restrict__ xyz2,
                                                 const float* __restrict__ flow,
                                                 const float* __restrict__ W1,
                                                 const float* __restrict__ W2,
                                                 float* __restrict__ out) {
    __shared__ float sW2[3 * 64];   // [j][o]
    __shared__ float sWx[64 * 3];   // [o][c]  (xyz columns of W1)
    int t = threadIdx.x;
    if (t < 192) sW2[t] = W2[t];
    if (t < 192) { int o = t / 3, c = t - o * 3; sWx[t] = W1[o * 67 + 64 + c]; }
    __syncthreads();

    int qL = t >> 2;          // 0..63
    int s  = t & 3;
    int b  = blockIdx.x >> 8; // 256 blocks per batch
    int q  = ((blockIdx.x & 255) << 6) + qL;

    const float* xq = xyz2 + (size_t)b * 3 * N2;
    float qx = xq[q], qy = xq[N2 + q], qz = xq[2 * N2 + q];

    const int* ip = g_idx + ((size_t)b * N2 + q) * KNN;
    int ik[8];
    {
        int4 a  = ((const int4*)ip)[0];
        int4 c4 = ((const int4*)ip)[1];
        ik[0] = a.x;  ik[1] = a.y;  ik[2] = a.z;  ik[3] = a.w;
        ik[4] = c4.x; ik[5] = c4.y; ik[6] = c4.z; ik[7] = c4.w;
    }

    const float* gb = g_gtab + (size_t)b * N1 * CF;

    float a0[8], a1[8], a2[8];
#pragma unroll
    for (int n = 0; n < 8; n++) { a0[n] = 0.f; a1[n] = 0.f; a2[n] = 0.f; }

    // sub-thread s owns o4 blocks [4s, 4s+4) = channels [16s, 16s+16)
#pragma unroll
    for (int oo = 0; oo < 4; oo++) {
        int o4 = s * 4 + oo;
        int ob = o4 * 4;
        float uu[4], wa[4], wb[4], wc[4];
#pragma unroll
        for (int i = 0; i < 4; i++) {
            int o = ob + i;
            uu[i] = fmaf(sWx[o * 3 + 2], qz, fmaf(sWx[o * 3 + 1], qy, sWx[o * 3] * qx));
            wa[i] = sW2[o];
            wb[i] = sW2[64 + o];
            wc[i] = sW2[128 + o];
        }
#pragma unroll
        for (int n = 0; n < 8; n++) {
            float4 g4 = ((const float4*)(gb + (size_t)ik[n] * CF))[o4];
            float h;
            h = g4.x - uu[0]; h = h >= 0.f ? h : 0.1f * h;
            a0[n] = fmaf(wa[0], h, a0[n]); a1[n] = fmaf(wb[0], h, a1[n]); a2[n] = fmaf(wc[0], h, a2[n]);
            h = g4.y - uu[1]; h = h >= 0.f ? h : 0.1f * h;
            a0[n] = fmaf(wa[1], h, a0[n]); a1[n] = fmaf(wb[1], h, a1[n]); a2[n] = fmaf(wc[1], h, a2[n]);
            h = g4.z - uu[2]; h = h >= 0.f ? h : 0.1f * h;
            a0[n] = fmaf(wa[2], h, a0[n]); a1[n] = fmaf(wb[2], h, a1[n]); a2[n] = fmaf(wc[2], h, a2[n]);
            h = g4.w - uu[3]; h = h >= 0.f ? h : 0.1f * h;
            a0[n] = fmaf(wa[3], h, a0[n]); a1[n] = fmaf(wb[3], h, a1[n]); a2[n] = fmaf(wc[3], h, a2[n]);
        }
    }

    // reduce the 4 sub-threads' partials (lanes 4k..4k+3 hold one query)
    const unsigned FULL = 0xffffffffu;
#pragma unroll
    for (int d = 1; d <= 2; d <<= 1) {
#pragma unroll
        for (int n = 0; n < 8; n++) {
            a0[n] += __shfl_xor_sync(FULL, a0[n], d);
            a1[n] += __shfl_xor_sync(FULL, a1[n], d);
            a2[n] += __shfl_xor_sync(FULL, a2[n], d);
        }
    }

    if (s == 0) {
        const float* fb = flow + (size_t)b * 3 * N1;
        float* ob_ = out + (size_t)b * 3 * N2;
        ob_[q]          = softmax_dot(a0, fb, ik);
        ob_[N2 + q]     = softmax_dot(a1, fb + N1, ik);
        ob_[2 * N2 + q] = softmax_dot(a2, fb + 2 * N1, ik);
    }
}

// ---------------------------------------------------------------------------
extern "C" void kernel_launch(void* const* d_in, const int* in_sizes, int n_in,
                              void* d_out, int out_size) {
    const float* xyz1  = (const float*)d_in[0];
    const float* xyz2  = (const float*)d_in[1];
    const float* feat1 = (const float*)d_in[2];
    const float* flow  = (const float*)d_in[3];
    const float* W1    = (const float*)d_in[4];
    const float* b1    = (const float*)d_in[5];
    const float* W2    = (const float*)d_in[6];
    // b2 (d_in[7]) unused: constant shift cancels in softmax over k.
    float* out = (float*)d_out;

    zero_kernel<<<1, 1024>>>();
    hist_kernel<<<(NB * N1 + 255) / 256, 256>>>(xyz1);
    bscan_kernel<<<NB, 512>>>();
    scatter_kernel<<<(NB * N1 + 255) / 256, 256>>>(xyz1);
    gmat_kernel<<<NB * 64, 256>>>(feat1, xyz1, W1, b1);
    knn_kernel<<<NB * 1024, 512>>>(xyz2);
    up_kernel<<<NB * 256, 256>>>(xyz2, flow, W1, W2, out);
}

// round 9
// speedup vs baseline: 1.2019x; 1.2019x over previous
#include <cuda_runtime.h>

#define NB 2
#define N1 4096
#define N2 16384
#define CF 64
#define KNN 8

#define BKN  512                  // x-buckets per batch
#define NBK  (NB * BKN)
#define XMIN -4.2f
#define BW   (8.4f / 512.0f)
#define BINV (512.0f / 8.4f)

// Scratch (static __device__ arrays per allocation rules)
__device__ int    g_bcnt[NBK], g_bcur[NBK];
__device__ int    g_tcid[NB * N1];
__device__ int2   g_bk[NBK];                // (offset, count) per bucket
__device__ float4 g_spts[NB * N1];          // bucket-sorted pts, w = orig idx bits
__device__ float  g_gtab[NB * N1 * CF];     // W1_feat@feat + W1_xyz@xyz1 + b1
__device__ int    g_idx[NB * N2 * KNN];     // knn indices (original index space)

__device__ __forceinline__ int xbucket(float x) {
    return min(max(__float2int_rd((x - XMIN) * BINV), 0), BKN - 1);
}

// ---------------------------------------------------------------------------
// bucket build: zero -> histogram -> scan -> scatter
// ---------------------------------------------------------------------------
__global__ void zero_kernel() {
    int i = threadIdx.x + blockIdx.x * 1024;
    if (i < NBK) { g_bcnt[i] = 0; g_bcur[i] = 0; }
}

__global__ void hist_kernel(const float* __restrict__ xyz1) {
    int i = blockIdx.x * 256 + threadIdx.x;
    if (i >= NB * N1) return;
    int b = i >> 12, j = i & (N1 - 1);
    float x = xyz1[(size_t)b * 3 * N1 + j];
    int cid = b * BKN + xbucket(x);
    g_tcid[i] = cid;
    atomicAdd(&g_bcnt[cid], 1);
}

__global__ void __launch_bounds__(512) bscan_kernel() {
    __shared__ int sh[BKN];
    int b = blockIdx.x, t = threadIdx.x;
    int v = g_bcnt[b * BKN + t];
    sh[t] = v;
    __syncthreads();
#pragma unroll
    for (int off = 1; off < BKN; off <<= 1) {
        int u = (t >= off) ? sh[t - off] : 0;
        __syncthreads();
        sh[t] += u;
        __syncthreads();
    }
    g_bk[b * BKN + t] = make_int2(sh[t] - v, v);   // exclusive offset, count
}

__global__ void scatter_kernel(const float* __restrict__ xyz1) {
    int i = blockIdx.x * 256 + threadIdx.x;
    if (i >= NB * N1) return;
    int b = i >> 12, j = i & (N1 - 1);
    const float* p = xyz1 + (size_t)b * 3 * N1;
    float x = p[j], y = p[N1 + j], z = p[2 * N1 + j];
    int cid = g_tcid[i];
    int pos = g_bk[cid].x + atomicAdd(&g_bcur[cid], 1);
    g_spts[b * N1 + pos] = make_float4(x, y, z, __int_as_float(j));
}

// ---------------------------------------------------------------------------
// Kernel 2: per-target transform  g[b][j][o] = sum_c W1[o][c]*in[c] + b1[o]
// ---------------------------------------------------------------------------
__global__ void __launch_bounds__(256) gmat_kernel(const float* __restrict__ feat1,
                                                   const float* __restrict__ xyz1,
                                                   const float* __restrict__ W1,
                                                   const float* __restrict__ b1) {
    __shared__ __align__(16) float sIn[67 * 64];
    __shared__ float sW[64 * 67];
    __shared__ float sB[64];

    int b  = blockIdx.x >> 6;
    int j0 = (blockIdx.x & 63) * 64;
    int t  = threadIdx.x;

    for (int i = t; i < 64 * 67; i += 256) sW[i] = W1[i];
    if (t < 64) sB[t] = b1[t];

    const float* fb = feat1 + (size_t)b * CF * N1;
    for (int i = t; i < 64 * 64; i += 256) {
        int c = i >> 6, j = i & 63;
        sIn[c * 64 + j] = fb[c * N1 + j0 + j];
    }
    const float* xb = xyz1 + (size_t)b * 3 * N1;
    if (t < 3 * 64) {
        int c = t >> 6, j = t & 63;
        sIn[(64 + c) * 64 + j] = xb[c * N1 + j0 + j];
    }
    __syncthreads();

    int o = t & 63, jg = t >> 6;
    float acc[16];
    float bb = sB[o];
#pragma unroll
    for (int ii = 0; ii < 16; ii++) acc[ii] = bb;

    for (int c = 0; c < 67; c++) {
        float w = sW[o * 67 + c];
        const float4* in4 = (const float4*)(sIn + c * 64 + jg * 16);
#pragma unroll
        for (int q4 = 0; q4 < 4; q4++) {
            float4 v = in4[q4];
            acc[q4 * 4 + 0] = fmaf(w, v.x, acc[q4 * 4 + 0]);
            acc[q4 * 4 + 1] = fmaf(w, v.y, acc[q4 * 4 + 1]);
            acc[q4 * 4 + 2] = fmaf(w, v.z, acc[q4 * 4 + 2]);
            acc[q4 * 4 + 3] = fmaf(w, v.w, acc[q4 * 4 + 3]);
        }
    }

    float* gp = g_gtab + ((size_t)b * N1 + j0 + jg * 16) * CF + o;
#pragma unroll
    for (int ii = 0; ii < 16; ii++) gp[ii * CF] = acc[ii];
}

// ---------------------------------------------------------------------------
// Kernel 3: top-8 KNN, one warp per query.
// Bucket-grouped array + CONTIGUOUS 32-point two-pointer chunks (full lane
// occupancy). Stop bound per side = distance from qx to the bucket edge of
// the next unscanned position (valid: positions are bucket-ordered).
// Extreme buckets use infinite edges so clamped outliers can't early-stop.
// Warm start: full-warp bitonic sort seeds the distributed top-8.
// ---------------------------------------------------------------------------
__device__ __forceinline__ void scan_chunk(const float4* __restrict__ SP,
                                           int base, int c,
                                           float qx, float qy, float qz,
                                           float& dk_own, int& ik_own,
                                           float& dk7, int lane) {
    const unsigned FULL = 0xffffffffu;
    float d = 3.4e38f; int iw = 0;
    if (lane < c) {
        float4 p = SP[base + lane];
        float dx = p.x - qx, dy = p.y - qy, dz = p.z - qz;
        d = fmaf(dz, dz, fmaf(dy, dy, dx * dx));
        iw = __float_as_int(p.w);
    }
    unsigned m = __ballot_sync(FULL, d < dk7);
    while (m) {                            // warp-uniform candidate loop
        int src = __ffs(m) - 1;
        m &= m - 1;
        float dc = __shfl_sync(FULL, d, src);
        if (dc < dk7) {                    // recheck vs tightened threshold
            int jc = __shfl_sync(FULL, iw, src);
            unsigned gt = __ballot_sync(FULL, (lane < 8) && (dk_own > dc));
            int pos = __ffs(gt) - 1;
            float upd = __shfl_up_sync(FULL, dk_own, 1);
            int   upj = __shfl_up_sync(FULL, ik_own, 1);
            if (lane < 8) {
                if (lane == pos)     { dk_own = dc;  ik_own = jc;  }
                else if (lane > pos) { dk_own = upd; ik_own = upj; }
            }
            dk7 = __shfl_sync(FULL, dk_own, 7);
        }
    }
}

__global__ void __launch_bounds__(512) knn_kernel(const float* __restrict__ xyz2) {
    const unsigned FULL = 0xffffffffu;
    int t    = threadIdx.x;
    int lane = t & 31;
    int w    = t >> 5;               // 0..15 : query within block
    int b    = blockIdx.x >> 10;     // 1024 blocks per batch
    int q    = ((blockIdx.x & 1023) << 4) + w;

    const float* xq = xyz2 + (size_t)b * 3 * N2;
    float qx = xq[q], qy = xq[N2 + q], qz = xq[2 * N2 + q];

    const float4* SP  = g_spts + b * N1;
    const int2*   BKT = g_bk   + b * BKN;

    int ib = xbucket(qx);
    int2 cb = BKT[ib];

    // --- warm start: bitonic sort first <=32 targets of the center bucket ---
    float d = 3.4e38f; int id = 0;
    {
        int c = min(cb.y, 32);
        if (lane < c) {
            float4 p = SP[cb.x + lane];
            float dx = p.x - qx, dy = p.y - qy, dz = p.z - qz;
            d = fmaf(dz, dz, fmaf(dy, dy, dx * dx));
            id = __float_as_int(p.w);
        }
#pragma unroll
        for (int k = 2; k <= 32; k <<= 1) {
#pragma unroll
            for (int j = k >> 1; j > 0; j >>= 1) {
                float od = __shfl_xor_sync(FULL, d, j);
                int   oi = __shfl_xor_sync(FULL, id, j);
                bool takeMin = ((lane & j) == 0) == ((lane & k) == 0);
                if ((od < d) == takeMin) { d = od; id = oi; }
            }
        }
    }
    float dk_own = d;                // lane r (r<8) holds list element r, ascending
    int   ik_own = id;               // original target index
    float dk7    = __shfl_sync(FULL, d, 7);

    // leftover of center bucket (contiguous chunks)
    int L = cb.x;                    // window [L, R) scanned
    int R = cb.x + min(cb.y, 32);
    int cbEnd = cb.x + cb.y;
    while (R < cbEnd) {
        int c = min(cbEnd - R, 32);
        scan_chunk(SP, R, c, qx, qy, qz, dk_own, ik_own, dk7, lane);
        R += c;
    }

    // --- two-pointer expansion over contiguous positions, bucket-edge bounds ---
#pragma unroll 1
    while (L > 0 || R < N1) {
        float gl = 3.4e38f, gr = 3.4e38f;
        if (L > 0) {
            int bk = xbucket(SP[L - 1].x);
            gl = (bk == BKN - 1) ? -3.4e38f : qx - (XMIN + (bk + 1) * BW);
        }
        if (R < N1) {
            int bk = xbucket(SP[R].x);
            gr = (bk == 0) ? -3.4e38f : (XMIN + bk * BW) - qx;
        }
        bool left = gl <= gr;
        float gap = fmaxf(left ? gl : gr, 0.f);
        if (gap * gap > dk7) break;
        if (left) {
            int nl = (L > 32) ? L - 32 : 0;
            scan_chunk(SP, nl, L - nl, qx, qy, qz, dk_own, ik_own, dk7, lane);
            L = nl;
        } else {
            int c = min(N1 - R, 32);
            scan_chunk(SP, R, c, qx, qy, qz, dk_own, ik_own, dk7, lane);
            R += c;
        }
    }

    if (lane < 8)
        g_idx[((size_t)b * N2 + q) * KNN + lane] = ik_own;
}

// ---------------------------------------------------------------------------
// Kernel 4: finalize, 4 sub-threads per query (16 channels each).
// h_n = lrelu(g[idx_n] - W1_xyz @ q);  w_j[n] = W2[j].h_n  (b2 cancels);
// softmax over n; dot with flow.
// ---------------------------------------------------------------------------
__device__ __forceinline__ float softmax_dot(const float (&w)[8],
                                             const float* __restrict__ f,
                                             const int (&ik)[8]) {
    float m = w[0];
#pragma unroll
    for (int n = 1; n < 8; n++) m = fmaxf(m, w[n]);
    float s = 0.f, acc = 0.f;
#pragma unroll
    for (int n = 0; n < 8; n++) {
        float e = __expf(w[n] - m);
        s += e;
        acc = fmaf(e, __ldg(f + ik[n]), acc);
    }
    return acc / s;
}

__global__ void __launch_bounds__(256, 3) up_kernel(const float* __restrict__ xyz2,
                                                    const float* __restrict__ flow,
                                                    const float* __restrict__ W1,
                                                    const float* __restrict__ W2,
                                                    float* __restrict__ out) {
    __shared__ float sW2[3 * 64];   // [j][o]
    __shared__ float sWx[64 * 3];   // [o][c]  (xyz columns of W1)
    int t = threadIdx.x;
    if (t < 192) sW2[t] = W2[t];
    if (t < 192) { int o = t / 3, c = t - o * 3; sWx[t] = W1[o * 67 + 64 + c]; }
    __syncthreads();

    int qL = t >> 2;          // 0..63
    int s  = t & 3;
    int b  = blockIdx.x >> 8; // 256 blocks per batch
    int q  = ((blockIdx.x & 255) << 6) + qL;

    const float* xq = xyz2 + (size_t)b * 3 * N2;
    float qx = xq[q], qy = xq[N2 + q], qz = xq[2 * N2 + q];

    const int* ip = g_idx + ((size_t)b * N2 + q) * KNN;
    int ik[8];
    {
        int4 a  = ((const int4*)ip)[0];
        int4 c4 = ((const int4*)ip)[1];
        ik[0] = a.x;  ik[1] = a.y;  ik[2] = a.z;  ik[3] = a.w;
        ik[4] = c4.x; ik[5] = c4.y; ik[6] = c4.z; ik[7] = c4.w;
    }

    const float* gb = g_gtab + (size_t)b * N1 * CF;

    float a0[8], a1[8], a2[8];
#pragma unroll
    for (int n = 0; n < 8; n++) { a0[n] = 0.f; a1[n] = 0.f; a2[n] = 0.f; }

    // sub-thread s owns o4 blocks [4s, 4s+4) = channels [16s, 16s+16)
#pragma unroll
    for (int oo = 0; oo < 4; oo++) {
        int o4 = s * 4 + oo;
        int ob = o4 * 4;
        float uu[4], wa[4], wb[4], wc[4];
#pragma unroll
        for (int i = 0; i < 4; i++) {
            int o = ob + i;
            uu[i] = fmaf(sWx[o * 3 + 2], qz, fmaf(sWx[o * 3 + 1], qy, sWx[o * 3] * qx));
            wa[i] = sW2[o];
            wb[i] = sW2[64 + o];
            wc[i] = sW2[128 + o];
        }
#pragma unroll
        for (int n = 0; n < 8; n++) {
            float4 g4 = ((const float4*)(gb + (size_t)ik[n] * CF))[o4];
            float h;
            h = g4.x - uu[0]; h = h >= 0.f ? h : 0.1f * h;
            a0[n] = fmaf(wa[0], h, a0[n]); a1[n] = fmaf(wb[0], h, a1[n]); a2[n] = fmaf(wc[0], h, a2[n]);
            h = g4.y - uu[1]; h = h >= 0.f ? h : 0.1f * h;
            a0[n] = fmaf(wa[1], h, a0[n]); a1[n] = fmaf(wb[1], h, a1[n]); a2[n] = fmaf(wc[1], h, a2[n]);
            h = g4.z - uu[2]; h = h >= 0.f ? h : 0.1f * h;
            a0[n] = fmaf(wa[2], h, a0[n]); a1[n] = fmaf(wb[2], h, a1[n]); a2[n] = fmaf(wc[2], h, a2[n]);
            h = g4.w - uu[3]; h = h >= 0.f ? h : 0.1f * h;
            a0[n] = fmaf(wa[3], h, a0[n]); a1[n] = fmaf(wb[3], h, a1[n]); a2[n] = fmaf(wc[3], h, a2[n]);
        }
    }

    // reduce the 4 sub-threads' partials (lanes 4k..4k+3 hold one query)
    const unsigned FULL = 0xffffffffu;
#pragma unroll
    for (int d = 1; d <= 2; d <<= 1) {
#pragma unroll
        for (int n = 0; n < 8; n++) {
            a0[n] += __shfl_xor_sync(FULL, a0[n], d);
            a1[n] += __shfl_xor_sync(FULL, a1[n], d);
            a2[n] += __shfl_xor_sync(FULL, a2[n], d);
        }
    }

    if (s == 0) {
        const float* fb = flow + (size_t)b * 3 * N1;
        float* ob_ = out + (size_t)b * 3 * N2;
        ob_[q]          = softmax_dot(a0, fb, ik);
        ob_[N2 + q]     = softmax_dot(a1, fb + N1, ik);
        ob_[2 * N2 + q] = softmax_dot(a2, fb + 2 * N1, ik);
    }
}

// ---------------------------------------------------------------------------
extern "C" void kernel_launch(void* const* d_in, const int* in_sizes, int n_in,
                              void* d_out, int out_size) {
    const float* xyz1  = (const float*)d_in[0];
    const float* xyz2  = (const float*)d_in[1];
    const float* feat1 = (const float*)d_in[2];
    const float* flow  = (const float*)d_in[3];
    const float* W1    = (const float*)d_in[4];
    const float* b1    = (const float*)d_in[5];
    const float* W2    = (const float*)d_in[6];
    // b2 (d_in[7]) unused: constant shift cancels in softmax over k.
    float* out = (float*)d_out;

    zero_kernel<<<1, 1024>>>();
    hist_kernel<<<(NB * N1 + 255) / 256, 256>>>(xyz1);
    bscan_kernel<<<NB, 512>>>();
    scatter_kernel<<<(NB * N1 + 255) / 256, 256>>>(xyz1);
    gmat_kernel<<<NB * 64, 256>>>(feat1, xyz1, W1, b1);
    knn_kernel<<<NB * 1024, 512>>>(xyz2);
    up_kernel<<<NB * 256, 256>>>(xyz2, flow, W1, W2, out);
}

// round 10
// speedup vs baseline: 2.0159x; 1.6772x over previous
#include <cuda_runtime.h>

#define NB 2
#define N1 4096
#define N2 16384
#define CF 64
#define KNN 8

#define GS    64                   // x-slabs per batch
#define GY    64                   // y-buckets per slab
#define NCELL (GS * GY)            // 4096 cells per batch
#define XMIN  -4.2f
#define BW    0.13125f             // 8.4 / 64
#define BINV  7.61904762f          // 1 / BW

// Scratch (static __device__ arrays per allocation rules)
__device__ int    g_ccnt[NB * NCELL], g_ccur[NB * NCELL];
__device__ int    g_tcid[NB * N1];
__device__ int    g_cst[NB * (NCELL + 1)];  // cell start offsets + sentinel
__device__ float4 g_spts[NB * N1];          // cell-sorted pts, w = orig idx bits
__device__ float  g_gtab[NB * N1 * CF];     // W1_feat@feat + W1_xyz@xyz1 + b1
__device__ int    g_idx[NB * N2 * KNN];     // knn indices (original index space)

__device__ __forceinline__ int bidx(float v) {
    return min(max(__float2int_rd((v - XMIN) * BINV), 0), GS - 1);
}

// ---------------------------------------------------------------------------
// cell build: zero -> histogram -> scan -> scatter
// ---------------------------------------------------------------------------
__global__ void zero_kernel() {
    int i = blockIdx.x * 1024 + threadIdx.x;
    if (i < NB * NCELL) { g_ccnt[i] = 0; g_ccur[i] = 0; }
}

__global__ void hist_kernel(const float* __restrict__ xyz1) {
    int i = blockIdx.x * 256 + threadIdx.x;
    if (i >= NB * N1) return;
    int b = i >> 12, j = i & (N1 - 1);
    const float* p = xyz1 + (size_t)b * 3 * N1;
    int cell = bidx(p[j]) * GY + bidx(p[N1 + j]);
    g_tcid[i] = cell;
    atomicAdd(&g_ccnt[b * NCELL + cell], 1);
}

__global__ void __launch_bounds__(1024) cscan_kernel() {
    __shared__ int tot[1024];
    int b = blockIdx.x, t = threadIdx.x;
    const int* cnt = g_ccnt + b * NCELL;
    int base = t * 4;
    int v0 = cnt[base], v1 = cnt[base + 1], v2 = cnt[base + 2], v3 = cnt[base + 3];
    int s0 = v0, s1 = s0 + v1, s2 = s1 + v2, s3 = s2 + v3;
    tot[t] = s3;
    __syncthreads();
#pragma unroll
    for (int off = 1; off < 1024; off <<= 1) {
        int u = (t >= off) ? tot[t - off] : 0;
        __syncthreads();
        tot[t] += u;
        __syncthreads();
    }
    int ex = tot[t] - s3;                       // exclusive prefix
    int* cst = g_cst + b * (NCELL + 1);
    cst[base]     = ex;
    cst[base + 1] = ex + s0;
    cst[base + 2] = ex + s1;
    cst[base + 3] = ex + s2;
    if (t == 1023) cst[NCELL] = ex + s3;        // sentinel (= N1)
}

__global__ void scatter_kernel(const float* __restrict__ xyz1) {
    int i = blockIdx.x * 256 + threadIdx.x;
    if (i >= NB * N1) return;
    int b = i >> 12, j = i & (N1 - 1);
    const float* p = xyz1 + (size_t)b * 3 * N1;
    float x = p[j], y = p[N1 + j], z = p[2 * N1 + j];
    int cell = g_tcid[i];
    int pos = g_cst[b * (NCELL + 1) + cell] + atomicAdd(&g_ccur[b * NCELL + cell], 1);
    g_spts[b * N1 + pos] = make_float4(x, y, z, __int_as_float(j));
}

// ---------------------------------------------------------------------------
// Kernel 2: per-target transform  g[b][j][o] = sum_c W1[o][c]*in[c] + b1[o]
// ---------------------------------------------------------------------------
__global__ void __launch_bounds__(256) gmat_kernel(const float* __restrict__ feat1,
                                                   const float* __restrict__ xyz1,
                                                   const float* __restrict__ W1,
                                                   const float* __restrict__ b1) {
    __shared__ __align__(16) float sIn[67 * 64];
    __shared__ float sW[64 * 67];
    __shared__ float sB[64];

    int b  = blockIdx.x >> 6;
    int j0 = (blockIdx.x & 63) * 64;
    int t  = threadIdx.x;

    for (int i = t; i < 64 * 67; i += 256) sW[i] = W1[i];
    if (t < 64) sB[t] = b1[t];

    const float* fb = feat1 + (size_t)b * CF * N1;
    for (int i = t; i < 64 * 64; i += 256) {
        int c = i >> 6, j = i & 63;
        sIn[c * 64 + j] = fb[c * N1 + j0 + j];
    }
    const float* xb = xyz1 + (size_t)b * 3 * N1;
    if (t < 3 * 64) {
        int c = t >> 6, j = t & 63;
        sIn[(64 + c) * 64 + j] = xb[c * N1 + j0 + j];
    }
    __syncthreads();

    int o = t & 63, jg = t >> 6;
    float acc[16];
    float bb = sB[o];
#pragma unroll
    for (int ii = 0; ii < 16; ii++) acc[ii] = bb;

    for (int c = 0; c < 67; c++) {
        float w = sW[o * 67 + c];
        const float4* in4 = (const float4*)(sIn + c * 64 + jg * 16);
#pragma unroll
        for (int q4 = 0; q4 < 4; q4++) {
            float4 v = in4[q4];
            acc[q4 * 4 + 0] = fmaf(w, v.x, acc[q4 * 4 + 0]);
            acc[q4 * 4 + 1] = fmaf(w, v.y, acc[q4 * 4 + 1]);
            acc[q4 * 4 + 2] = fmaf(w, v.z, acc[q4 * 4 + 2]);
            acc[q4 * 4 + 3] = fmaf(w, v.w, acc[q4 * 4 + 3]);
        }
    }

    float* gp = g_gtab + ((size_t)b * N1 + j0 + jg * 16) * CF + o;
#pragma unroll
    for (int ii = 0; ii < 16; ii++) gp[ii * CF] = acc[ii];
}

// ---------------------------------------------------------------------------
// Kernel 3: top-8 KNN, one warp per query, 2-D (x-slab, y-bucket) pruning.
// Storage is slab-major so each slab's y-range is CONTIGUOUS -> full-width
// 32-lane chunks. Per-slab y-bound is exact: unscanned points have
// dy^2 > dk7 - dxmin^2 (bucket-edge distances; clamped extreme buckets are
// handled since their points lie even farther outside the scanned range).
// Warm start: full-warp bitonic sort around the query's own cell.
// ---------------------------------------------------------------------------
__device__ __forceinline__ void scan_chunk(const float4* __restrict__ SP,
                                           int base, int c, int wst, int wen,
                                           float qx, float qy, float qz,
                                           float& dk_own, int& ik_own,
                                           float& dk7, int lane) {
    const unsigned FULL = 0xffffffffu;
    float d = 3.4e38f; int iw = 0;
    int pos = base + lane;
    if (lane < c && (pos < wst || pos >= wen)) {    // skip warm-start window
        float4 p = SP[pos];
        float dx = p.x - qx, dy = p.y - qy, dz = p.z - qz;
        d = fmaf(dz, dz, fmaf(dy, dy, dx * dx));
        iw = __float_as_int(p.w);
    }
    unsigned m = __ballot_sync(FULL, d < dk7);
    while (m) {                            // warp-uniform candidate loop
        int src = __ffs(m) - 1;
        m &= m - 1;
        float dc = __shfl_sync(FULL, d, src);
        if (dc < dk7) {                    // recheck vs tightened threshold
            int jc = __shfl_sync(FULL, iw, src);
            unsigned gt = __ballot_sync(FULL, (lane < 8) && (dk_own > dc));
            int pp = __ffs(gt) - 1;
            float upd = __shfl_up_sync(FULL, dk_own, 1);
            int   upj = __shfl_up_sync(FULL, ik_own, 1);
            if (lane < 8) {
                if (lane == pp)     { dk_own = dc;  ik_own = jc;  }
                else if (lane > pp) { dk_own = upd; ik_own = upj; }
            }
            dk7 = __shfl_sync(FULL, dk_own, 7);
        }
    }
}

__device__ __forceinline__ void process_slab(const float4* __restrict__ SP,
                                             const int* __restrict__ CST,
                                             int s, float gap, int wst, int wen,
                                             float qx, float qy, float qz,
                                             float& dk_own, int& ik_own,
                                             float& dk7, int lane) {
    float bb = dk7 - gap * gap;            // >= 0 at call sites
    float bound = sqrtf(bb) + 1e-5f;       // inflated vs rounding
    int ylo = bidx(qy - bound);
    int yhi = bidx(qy + bound);
    int r0 = CST[s * GY + ylo];
    int r1 = CST[s * GY + yhi + 1];
    for (int p = r0; p < r1; p += 32)
        scan_chunk(SP, p, min(r1 - p, 32), wst, wen,
                   qx, qy, qz, dk_own, ik_own, dk7, lane);
}

__global__ void __launch_bounds__(512) knn_kernel(const float* __restrict__ xyz2) {
    const unsigned FULL = 0xffffffffu;
    int t    = threadIdx.x;
    int lane = t & 31;
    int w    = t >> 5;               // 0..15 : query within block
    int b    = blockIdx.x >> 10;     // 1024 blocks per batch
    int q    = ((blockIdx.x & 1023) << 4) + w;

    const float* xq = xyz2 + (size_t)b * 3 * N2;
    float qx = xq[q], qy = xq[N2 + q], qz = xq[2 * N2 + q];

    const float4* SP  = g_spts + b * N1;
    const int*    CST = g_cst  + b * (NCELL + 1);

    int s  = bidx(qx);
    int yb = bidx(qy);
    int ss = CST[s * GY];            // slab start
    int se = CST[(s + 1) * GY];      // slab end (sentinel-safe for s=63)
    int cs = CST[s * GY + yb];       // query's cell start

    // --- warm start: bitonic sort of <=32 positions around the query cell ---
    int cnt = min(se - ss, 32);
    int wst = min(max(cs - 16, ss), se - cnt);
    int wen = wst + cnt;
    float d = 3.4e38f; int id = 0;
    if (lane < cnt) {
        float4 p = SP[wst + lane];
        float dx = p.x - qx, dy = p.y - qy, dz = p.z - qz;
        d = fmaf(dz, dz, fmaf(dy, dy, dx * dx));
        id = __float_as_int(p.w);
    }
#pragma unroll
    for (int k = 2; k <= 32; k <<= 1) {
#pragma unroll
        for (int j = k >> 1; j > 0; j >>= 1) {
            float od = __shfl_xor_sync(FULL, d, j);
            int   oi = __shfl_xor_sync(FULL, id, j);
            bool takeMin = ((lane & j) == 0) == ((lane & k) == 0);
            if ((od < d) == takeMin) { d = od; id = oi; }
        }
    }
    float dk_own = d;                // lane r (r<8) holds list element r, ascending
    int   ik_own = id;               // original target index
    float dk7    = __shfl_sync(FULL, d, 7);

    // center slab remainder (warm window excluded inside scan_chunk)
    process_slab(SP, CST, s, 0.f, wst, wen, qx, qy, qz, dk_own, ik_own, dk7, lane);

    // --- two-pointer slab expansion with exact x-edge bounds ---
    int sl = s, sr = s;
#pragma unroll 1
    while (sl > 0 || sr < GS - 1) {
        float gl = (sl > 0)      ? qx - (XMIN + sl * BW)       : 3.4e38f;
        float gr = (sr < GS - 1) ? (XMIN + (sr + 1) * BW) - qx : 3.4e38f;
        bool left = gl <= gr;
        float gap = fmaxf(left ? gl : gr, 0.f);
        if (gap * gap > dk7) break;
        int ns = left ? --sl : ++sr;
        process_slab(SP, CST, ns, gap, -1, -1, qx, qy, qz, dk_own, ik_own, dk7, lane);
    }

    if (lane < 8)
        g_idx[((size_t)b * N2 + q) * KNN + lane] = ik_own;
}

// ---------------------------------------------------------------------------
// Kernel 4: finalize, 4 sub-threads per query (16 channels each).
// h_n = lrelu(g[idx_n] - W1_xyz @ q);  w_j[n] = W2[j].h_n  (b2 cancels);
// softmax over n; dot with flow.
// ---------------------------------------------------------------------------
__device__ __forceinline__ float softmax_dot(const float (&w)[8],
                                             const float* __restrict__ f,
                                             const int (&ik)[8]) {
    float m = w[0];
#pragma unroll
    for (int n = 1; n < 8; n++) m = fmaxf(m, w[n]);
    float s = 0.f, acc = 0.f;
#pragma unroll
    for (int n = 0; n < 8; n++) {
        float e = __expf(w[n] - m);
        s += e;
        acc = fmaf(e, __ldg(f + ik[n]), acc);
    }
    return acc / s;
}

__global__ void __launch_bounds__(256, 3) up_kernel(const float* __restrict__ xyz2,
                                                    const float* __restrict__ flow,
                                                    const float* __restrict__ W1,
                                                    const float* __restrict__ W2,
                                                    float* __restrict__ out) {
    __shared__ float sW2[3 * 64];   // [j][o]
    __shared__ float sWx[64 * 3];   // [o][c]  (xyz columns of W1)
    int t = threadIdx.x;
    if (t < 192) sW2[t] = W2[t];
    if (t < 192) { int o = t / 3, c = t - o * 3; sWx[t] = W1[o * 67 + 64 + c]; }
    __syncthreads();

    int qL = t >> 2;          // 0..63
    int s  = t & 3;
    int b  = blockIdx.x >> 8; // 256 blocks per batch
    int q  = ((blockIdx.x & 255) << 6) + qL;

    const float* xq = xyz2 + (size_t)b * 3 * N2;
    float qx = xq[q], qy = xq[N2 + q], qz = xq[2 * N2 + q];

    const int* ip = g_idx + ((size_t)b * N2 + q) * KNN;
    int ik[8];
    {
        int4 a  = ((const int4*)ip)[0];
        int4 c4 = ((const int4*)ip)[1];
        ik[0] = a.x;  ik[1] = a.y;  ik[2] = a.z;  ik[3] = a.w;
        ik[4] = c4.x; ik[5] = c4.y; ik[6] = c4.z; ik[7] = c4.w;
    }

    const float* gb = g_gtab + (size_t)b * N1 * CF;

    float a0[8], a1[8], a2[8];
#pragma unroll
    for (int n = 0; n < 8; n++) { a0[n] = 0.f; a1[n] = 0.f; a2[n] = 0.f; }

    // sub-thread s owns o4 blocks [4s, 4s+4) = channels [16s, 16s+16)
#pragma unroll
    for (int oo = 0; oo < 4; oo++) {
        int o4 = s * 4 + oo;
        int ob = o4 * 4;
        float uu[4], wa[4], wb[4], wc[4];
#pragma unroll
        for (int i = 0; i < 4; i++) {
            int o = ob + i;
            uu[i] = fmaf(sWx[o * 3 + 2], qz, fmaf(sWx[o * 3 + 1], qy, sWx[o * 3] * qx));
            wa[i] = sW2[o];
            wb[i] = sW2[64 + o];
            wc[i] = sW2[128 + o];
        }
#pragma unroll
        for (int n = 0; n < 8; n++) {
            float4 g4 = ((const float4*)(gb + (size_t)ik[n] * CF))[o4];
            float h;
            h = g4.x - uu[0]; h = h >= 0.f ? h : 0.1f * h;
            a0[n] = fmaf(wa[0], h, a0[n]); a1[n] = fmaf(wb[0], h, a1[n]); a2[n] = fmaf(wc[0], h, a2[n]);
            h = g4.y - uu[1]; h = h >= 0.f ? h : 0.1f * h;
            a0[n] = fmaf(wa[1], h, a0[n]); a1[n] = fmaf(wb[1], h, a1[n]); a2[n] = fmaf(wc[1], h, a2[n]);
            h = g4.z - uu[2]; h = h >= 0.f ? h : 0.1f * h;
            a0[n] = fmaf(wa[2], h, a0[n]); a1[n] = fmaf(wb[2], h, a1[n]); a2[n] = fmaf(wc[2], h, a2[n]);
            h = g4.w - uu[3]; h = h >= 0.f ? h : 0.1f * h;
            a0[n] = fmaf(wa[3], h, a0[n]); a1[n] = fmaf(wb[3], h, a1[n]); a2[n] = fmaf(wc[3], h, a2[n]);
        }
    }

    // reduce the 4 sub-threads' partials (lanes 4k..4k+3 hold one query)
    const unsigned FULL = 0xffffffffu;
#pragma unroll
    for (int d = 1; d <= 2; d <<= 1) {
#pragma unroll
        for (int n = 0; n < 8; n++) {
            a0[n] += __shfl_xor_sync(FULL, a0[n], d);
            a1[n] += __shfl_xor_sync(FULL, a1[n], d);
            a2[n] += __shfl_xor_sync(FULL, a2[n], d);
        }
    }

    if (s == 0) {
        const float* fb = flow + (size_t)b * 3 * N1;
        float* ob_ = out + (size_t)b * 3 * N2;
        ob_[q]          = softmax_dot(a0, fb, ik);
        ob_[N2 + q]     = softmax_dot(a1, fb + N1, ik);
        ob_[2 * N2 + q] = softmax_dot(a2, fb + 2 * N1, ik);
    }
}

// ---------------------------------------------------------------------------
extern "C" void kernel_launch(void* const* d_in, const int* in_sizes, int n_in,
                              void* d_out, int out_size) {
    const float* xyz1  = (const float*)d_in[0];
    const float* xyz2  = (const float*)d_in[1];
    const float* feat1 = (const float*)d_in[2];
    const float* flow  = (const float*)d_in[3];
    const float* W1    = (const float*)d_in[4];
    const float* b1    = (const float*)d_in[5];
    const float* W2    = (const float*)d_in[6];
    // b2 (d_in[7]) unused: constant shift cancels in softmax over k.
    float* out = (float*)d_out;

    zero_kernel<<<(NB * NCELL + 1023) / 1024, 1024>>>();
    hist_kernel<<<(NB * N1 + 255) / 256, 256>>>(xyz1);
    cscan_kernel<<<NB, 1024>>>();
    scatter_kernel<<<(NB * N1 + 255) / 256, 256>>>(xyz1);
    gmat_kernel<<<NB * 64, 256>>>(feat1, xyz1, W1, b1);
    knn_kernel<<<NB * 1024, 512>>>(xyz2);
    up_kernel<<<NB * 256, 256>>>(xyz2, flow, W1, W2, out);
}